// round 17
// baseline (speedup 1.0000x reference)
#include <cuda_runtime.h>
#include <cfloat>

// Problem constants (from reference)
#define PB 7      // pooled bins per dim
#define HH 50
#define WW 50
#define CC 512
#define BB 2
#define RR 64
#define C4 (CC / 4)     // 128 float4 per pixel
#define NBINS (BB * RR * PB * PB)   // 6272
#define NCTA  (NBINS / 4)           // 1568: 4 bins per CTA

// R12 layout (best: 10.21us) with CROSS-BIN LOAD INTERLEAVING:
// the 4 bins are processed as 2 pairs; within a pair both bins' gathers run
// as one unrolled 4x4 predicated stream with two independent accumulators,
// so both bins' loads are in flight together (2 L2 round trips per CTA
// instead of 4 — the serialization every previous round left in place).
//
// CTA i handles bins {i, i+1568, i+3136, i+4704}; 1568 = 32*49 so all share
// one (py,px). All 4 rois are loaded up front (independent LDGs).
//
// Integer bin bounds ys = py*h/7 == reference fp32 trunc(py*(h/7.0f)) for
// h in [7,25]: exact when 7|h, else py*h/7 is >=1/7 from any integer, far
// beyond fp32 rounding error. (Validated rel_err=0.0 across rounds.)
//
// Facts proved from input ranges: extent in [7,26) => sy,sx in [1,4];
// window always fully in-bounds (max index y0+h-1 <= 48 < 50).

__device__ __forceinline__ void vmax(float4& m, float4 v) {
    m.x = fmaxf(m.x, v.x);
    m.y = fmaxf(m.y, v.y);
    m.z = fmaxf(m.z, v.z);
    m.w = fmaxf(m.w, v.w);
}

struct Bin {
    const float4* p;   // base pointer (window top-left, this thread's slice)
    int sy, sx;
};

// Compute one bin's window from a roi. (py,px) fixed per CTA.
__device__ __forceinline__ Bin make_bin(const float4* __restrict__ fm, int4 roi,
                                        int rid, int py, int px,
                                        bool lasty, bool lastx, int c4) {
    int y0 = roi.x, x0 = roi.y, h = roi.z, w = roi.w;
    int ys = (py * h) / PB;
    int ye = lasty ? h : ((py + 1) * h) / PB;
    int xs = (px * w) / PB;
    int xe = lastx ? w : ((px + 1) * w) / PB;
    Bin b;
    b.sy = max(ye - ys, 1);
    b.sx = max(xe - xs, 1);
    b.p  = fm + ((size_t)(((rid >> 6) * HH + (y0 + ys)) * WW + (x0 + xs))) * C4 + c4;
    return b;
}

// Interleaved gather of two independent bins: one unrolled 4x4 predicated
// stream, two accumulators. Loads of a/b never depend on any fmax result,
// so both gathers stay in flight together.
__device__ __forceinline__ void pairmax(Bin A, Bin B, float4& ma, float4& mb) {
    ma = make_float4(-FLT_MAX, -FLT_MAX, -FLT_MAX, -FLT_MAX);
    mb = ma;
    #pragma unroll
    for (int dy = 0; dy < 4; ++dy) {
        #pragma unroll
        for (int dx = 0; dx < 4; ++dx) {
            if (dy < A.sy && dx < A.sx)
                vmax(ma, __ldg(A.p + (dy * WW + dx) * C4));
            if (dy < B.sy && dx < B.sx)
                vmax(mb, __ldg(B.p + (dy * WW + dx) * C4));
        }
    }
}

__global__ __launch_bounds__(C4) void roipool_kernel(
    const float4* __restrict__ fm,    // (B,H,W,C) as float4
    const int*    __restrict__ rois,  // (B,R,4) int32: y0,x0,h,w
    float4*       __restrict__ out)   // (B,R,P,P,C) as float4
{
    int binbase = blockIdx.x;         // 0..1567
    int px   = binbase % PB;
    int py   = (binbase / PB) % PB;
    int rid0 = binbase / (PB * PB);   // 0..31; bins use rid0 + 32k

    int c4 = threadIdx.x;             // 0..127
    bool lasty = (py == PB - 1);
    bool lastx = (px == PB - 1);
    int obin = py * PB + px;

    // All 4 rois up front — independent loads, one L2 trip total.
    int4 roi0 = __ldg((const int4*)(rois + (rid0      ) * 4));
    int4 roi1 = __ldg((const int4*)(rois + (rid0 + 32 ) * 4));
    int4 roi2 = __ldg((const int4*)(rois + (rid0 + 64 ) * 4));
    int4 roi3 = __ldg((const int4*)(rois + (rid0 + 96 ) * 4));

    // Pair 0: bins (rid0, rid0+32)
    {
        Bin A = make_bin(fm, roi0, rid0,      py, px, lasty, lastx, c4);
        Bin B = make_bin(fm, roi1, rid0 + 32, py, px, lasty, lastx, c4);
        float4 ma, mb;
        pairmax(A, B, ma, mb);
        out[(size_t)((rid0      ) * (PB * PB) + obin) * C4 + c4] = ma;
        out[(size_t)((rid0 + 32 ) * (PB * PB) + obin) * C4 + c4] = mb;
    }

    // Pair 1: bins (rid0+64, rid0+96)
    {
        Bin A = make_bin(fm, roi2, rid0 + 64, py, px, lasty, lastx, c4);
        Bin B = make_bin(fm, roi3, rid0 + 96, py, px, lasty, lastx, c4);
        float4 ma, mb;
        pairmax(A, B, ma, mb);
        out[(size_t)((rid0 + 64 ) * (PB * PB) + obin) * C4 + c4] = ma;
        out[(size_t)((rid0 + 96 ) * (PB * PB) + obin) * C4 + c4] = mb;
    }
}

extern "C" void kernel_launch(void* const* d_in, const int* in_sizes, int n_in,
                              void* d_out, int out_size) {
    const float4* fm   = (const float4*)d_in[0];  // x_maps float32 (2,50,50,512)
    const int*    rois = (const int*)d_in[1];     // x_rois int32 (2,64,4)
    float4*       out  = (float4*)d_out;          // (2,64,7,7,512) float32

    roipool_kernel<<<NCTA, C4>>>(fm, rois, out);
}